// round 14
// baseline (speedup 1.0000x reference)
#include <cuda_runtime.h>
#include <cuda_fp16.h>
#include <math.h>
#include <stdint.h>

// Problem constants
constexpr int Bb = 256;    // batch
constexpr int Tt = 512;    // seq len
constexpr int Ii = 256;    // input size
constexpr int Hh = 512;    // hidden size
constexpr int Oo = 256;    // output size
constexpr int G4 = 4 * Hh; // 2048 packed gate width, n = j*4 + g (0=f,1=i,2=c,3=o)

// ---------------------------------------------------------------------------
// Device scratch
// ---------------------------------------------------------------------------
__device__ __half g_gx[(size_t)Tt * Bb * G4];   // 512 MB: input projections fp16, m = t*B+b
__device__ __half g_xh[(size_t)Tt * Bb * Ii];   // 64 MB: x fp16, [m][k]
__device__ __half g_Wxh[(size_t)G4 * Ii];       // W_x packed [n][k] fp16
__device__ __half g_Whh[(size_t)G4 * Hh];       // W_h packed [n][k] fp16
__device__ float  g_biasp[G4];                  // bias packed [n]
__device__ __half g_hh[2][Bb * Hh];             // double-buffered hidden (fp16)
__device__ unsigned g_ctrs[8];                  // per-b-group barrier counters

// ---------------------------------------------------------------------------
// PTX helpers (base PTX only: valid at compute_103 virtual arch)
// ---------------------------------------------------------------------------
__device__ __forceinline__ uint32_t smem_u32(const void* p) {
    uint32_t a;
    asm("{ .reg .u64 t; cvta.to.shared.u64 t, %1; cvt.u32.u64 %0, t; }" : "=r"(a) : "l"(p));
    return a;
}
__device__ __forceinline__ void cp16(uint32_t dst, const void* src) {
    asm volatile("cp.async.cg.shared.global [%0], [%1], 16;" :: "r"(dst), "l"(src));
}
#define CP_COMMIT() asm volatile("cp.async.commit_group;" ::: "memory")
#define CP_WAIT(n)  asm volatile("cp.async.wait_group %0;" :: "n"(n) : "memory")

__device__ __forceinline__ void ldm_x4(uint32_t (&r)[4], uint32_t addr) {
    asm volatile("ldmatrix.sync.aligned.m8n8.x4.shared.b16 {%0,%1,%2,%3}, [%4];"
        : "=r"(r[0]), "=r"(r[1]), "=r"(r[2]), "=r"(r[3]) : "r"(addr));
}
__device__ __forceinline__ void mma16816(float (&c)[4], const uint32_t (&a)[4], const uint32_t* b) {
    asm volatile("mma.sync.aligned.m16n8k16.row.col.f32.f16.f16.f32 "
        "{%0,%1,%2,%3}, {%4,%5,%6,%7}, {%8,%9}, {%0,%1,%2,%3};"
        : "+f"(c[0]), "+f"(c[1]), "+f"(c[2]), "+f"(c[3])
        : "r"(a[0]), "r"(a[1]), "r"(a[2]), "r"(a[3]), "r"(b[0]), "r"(b[1]));
}

// Fast activations (err ~1e-7, below fp16 noise)
__device__ __forceinline__ float ex2f(float x) { float y; asm("ex2.approx.f32 %0, %1;" : "=f"(y) : "f"(x)); return y; }
__device__ __forceinline__ float rcpf(float x) { float y; asm("rcp.approx.f32 %0, %1;" : "=f"(y) : "f"(x)); return y; }
__device__ __forceinline__ float sigf(float x)   { return rcpf(1.0f + ex2f(-1.4426950408889634f * x)); }
__device__ __forceinline__ float tanhf_(float x) { return __fmaf_rn(2.0f, sigf(2.0f * x), -1.0f); }

// SMEM tile geometry: 64 data halves + 8 pad per row -> conflict-free ldmatrix
constexpr int RSTRIDE = 144;   // bytes per smem row

__device__ __forceinline__ uint32_t a_lane_off(int lane) {
    return (uint32_t)(((lane & 7) + ((lane >> 3) & 1) * 8) * RSTRIDE + (lane >> 4) * 16);
}
__device__ __forceinline__ uint32_t b_lane_off(int lane) {
    return (uint32_t)(((lane & 7) + ((lane >> 4) & 1) * 8) * RSTRIDE + ((lane >> 3) & 1) * 16);
}

// ---------------------------------------------------------------------------
// Packing
// ---------------------------------------------------------------------------
__global__ void pack_x(const float* __restrict__ x) {
    size_t e = ((size_t)blockIdx.x * blockDim.x + threadIdx.x) * 4;
    if (e >= (size_t)Tt * Bb * Ii) return;
    int    k  = (int)(e & 255);
    size_t md = e >> 8;
    int    b  = (int)(md & 255);
    int    t  = (int)(md >> 8);
    float4 v = *(const float4*)(x + ((size_t)b * Tt + t) * Ii + k);
    *(__half2*)(g_xh + e)     = __floats2half2_rn(v.x, v.y);
    *(__half2*)(g_xh + e + 2) = __floats2half2_rn(v.z, v.w);
}

// Tiled transpose pack for weights: 64n x 64k tiles through smem,
// fully coalesced 16B writes.
__global__ void pack_w(const float* __restrict__ Wf, const float* __restrict__ bf,
                       const float* __restrict__ Wi, const float* __restrict__ bi,
                       const float* __restrict__ Wc, const float* __restrict__ bc,
                       const float* __restrict__ Wo, const float* __restrict__ bo) {
    __shared__ __half ws[64][72];   // [kk][nn]
    const int n0 = blockIdx.x * 64;
    const int k0 = blockIdx.y * 64;
    const float* Ws[4] = {Wf, Wi, Wc, Wo};

#pragma unroll
    for (int p = 0; p < 16; p++) {
        int idx = threadIdx.x + p * 256;
        int kk = idx >> 6, nn = idx & 63;
        int n = n0 + nn, g = n & 3, j = n >> 2;
        ws[kk][nn] = __float2half_rn(Ws[g][(size_t)(k0 + kk) * Hh + j]);
    }
    __syncthreads();

    const int nn = threadIdx.x >> 2, kq = threadIdx.x & 3;
    const int n = n0 + nn;
    __align__(16) __half tmp[16];
#pragma unroll
    for (int i = 0; i < 16; i++) tmp[i] = ws[kq * 16 + i][nn];
    if (k0 < Ii) {
        __half* dst = g_Wxh + (size_t)n * Ii + k0 + kq * 16;
        *(uint4*)dst       = *(uint4*)tmp;
        *(uint4*)(dst + 8) = *(uint4*)(tmp + 8);
    } else {
        __half* dst = g_Whh + (size_t)n * Hh + (k0 - Ii) + kq * 16;
        *(uint4*)dst       = *(uint4*)tmp;
        *(uint4*)(dst + 8) = *(uint4*)(tmp + 8);
    }

    if (blockIdx.y == 0 && threadIdx.x < 64) {
        int nb = n0 + threadIdx.x, g = nb & 3, j = nb >> 2;
        const float* bs[4] = {bf, bi, bc, bo};
        g_biasp[nb] = bs[g][j];
    }
}

__global__ void zero_state() {
    int i = blockIdx.x * blockDim.x + threadIdx.x;
    if (i < 8) g_ctrs[i] = 0;
    if (i < Bb * Hh) g_hh[0][i] = __float2half_rn(0.0f);
}

// ---------------------------------------------------------------------------
// Phase 1 (B-resident streaming): gx[m][n] = fp16(sum_k xh[m][k]*Wxh[n][k]+b)
//   Grid 16(n-tiles of 128) x 16(m-groups of 64 m-tiles) = 256 CTAs, 2/SM.
//   W_x tile (128n x 256k = 72KB) resident; A streamed as 16KB chunks through
//   a 2-buffer pipeline (look-ahead 2, one CP_WAIT per chunk). 256 thr,
//   8 warps (2m x 4n, 64x32 warp tiles). B L2 traffic: 1GB -> 18MB.
// ---------------------------------------------------------------------------
constexpr int P4_CH = 128 * RSTRIDE;               // 18432 B (128 rows x 64 halves)
constexpr uint32_t P4_B  = 0;                      // B resident: 4 chunks = 73728
constexpr uint32_t P4_A0 = 4 * (uint32_t)P4_CH;    // A buf0
constexpr uint32_t P4_A1 = 5 * (uint32_t)P4_CH;    // A buf1
constexpr int P1_SMEM = 6 * P4_CH;                 // 110592 B -> 2 CTAs/SM

__global__ void __launch_bounds__(256) phase1_mma() {
    extern __shared__ __align__(128) char smem[];
    const uint32_t sb = smem_u32(smem);
    const int tid = threadIdx.x, lane = tid & 31, wid = tid >> 5;
    const int wm = wid >> 2, wn = wid & 3;
    const int n0 = blockIdx.x * 128;
    const int mt0 = blockIdx.y * 64;     // first m-tile of this group

    const uint32_t aoff = a_lane_off(lane);
    const uint32_t boff = b_lane_off(lane);

    // Resident B: W_x tile 128(n) x 256(k), 4 chunks, loaded once (1 group).
#pragma unroll
    for (int q = 0; q < 16; q++) {
        int i = tid + q * 256;           // 0..4095
        int c = i >> 10, r = (i >> 3) & 127, g = i & 7;
        cp16(sb + P4_B + c * P4_CH + r * RSTRIDE + g * 16,
             g_Wxh + (size_t)(n0 + r) * Ii + c * 64 + g * 8);
    }
    CP_COMMIT();

    // A chunk ci = mt*4 + kc (mt local 0..63): 1024 cp16 into buf(ci&1).
    auto load_achunk = [&](int ci) {
        const int m0 = (mt0 + (ci >> 2)) * 128;
        const int kc = ci & 3;
        const uint32_t buf = (ci & 1) ? P4_A1 : P4_A0;
#pragma unroll
        for (int q = 0; q < 4; q++) {
            int i = tid + q * 256, r = i >> 3, g = i & 7;
            cp16(sb + buf + r * RSTRIDE + g * 16,
                 g_xh + (size_t)(m0 + r) * Ii + kc * 64 + g * 8);
        }
        CP_COMMIT();
    };

    load_achunk(0);
    load_achunk(1);

    float acc[4][4][4] = {};
    for (int ci = 0; ci < 256; ci++) {
        CP_WAIT(1);                      // chunk ci resident (B done at ci=0)
        __syncthreads();

        const uint32_t Ab = sb + ((ci & 1) ? P4_A1 : P4_A0);
        const uint32_t Bx = sb + P4_B + (ci & 3) * P4_CH;
#pragma unroll
        for (int kb = 0; kb < 64; kb += 16) {
            uint32_t a[4][4], b[2][4];
#pragma unroll
            for (int mi = 0; mi < 4; mi++)
                ldm_x4(a[mi], Ab + (wm * 64 + mi * 16) * RSTRIDE + kb * 2 + aoff);
#pragma unroll
            for (int bi = 0; bi < 2; bi++)
                ldm_x4(b[bi], Bx + (wn * 32 + bi * 16) * RSTRIDE + kb * 2 + boff);
#pragma unroll
            for (int mi = 0; mi < 4; mi++)
#pragma unroll
                for (int ni = 0; ni < 4; ni++)
                    mma16816(acc[mi][ni], a[mi], &b[ni >> 1][(ni & 1) * 2]);
        }
        __syncthreads();
        if (ci + 2 < 256) load_achunk(ci + 2);

        if ((ci & 3) == 3) {
            // Epilogue for m-tile ci>>2: fp16 store with bias, reset acc.
            const int m0 = (mt0 + (ci >> 2)) * 128;
            const int r0 = wm * 64 + (lane >> 2);
            const int c0 = wn * 32 + 2 * (lane & 3);
#pragma unroll
            for (int mi = 0; mi < 4; mi++) {
#pragma unroll
                for (int ni = 0; ni < 4; ni++) {
                    const int n = n0 + c0 + ni * 8;
                    const float2 bv = *(const float2*)&g_biasp[n];
                    const int m = m0 + r0 + mi * 16;
                    *(__half2*)(g_gx + (size_t)m * G4 + n) =
                        __floats2half2_rn(acc[mi][ni][0] + bv.x, acc[mi][ni][1] + bv.y);
                    *(__half2*)(g_gx + (size_t)(m + 8) * G4 + n) =
                        __floats2half2_rn(acc[mi][ni][2] + bv.x, acc[mi][ni][3] + bv.y);
                    acc[mi][ni][0] = 0.0f; acc[mi][ni][1] = 0.0f;
                    acc[mi][ni][2] = 0.0f; acc[mi][ni][3] = 0.0f;
                }
            }
        }
    }
}

// ---------------------------------------------------------------------------
// Persistent recurrence (R7, verbatim): 128 CTAs = 16 n-tiles(128) x 8
// b-groups(32), all 512 steps. 128 threads (4 warps along n, 32x32 warp
// tiles). W_h tile (144KB) resident in smem; c in registers; gx prefetched
// into registers from global; per-b-group spin barrier (fan-in 16).
// ---------------------------------------------------------------------------
constexpr int A_CHUNK = 32 * RSTRIDE;                 // 4608 B  (32 rows x 64 halves)
constexpr int B_CHUNK = 128 * RSTRIDE;                // 18432 B (128 rows x 64 halves)
constexpr uint32_t PS_A  = 0;                         // A (h) chunks: 8 x 4608 = 36864
constexpr uint32_t PS_B  = 8 * A_CHUNK;               // B (Wh) resident: 8 x 18432 = 147456
constexpr uint32_t PS_CS = PS_B + 8 * B_CHUNK;        // Cs exchange: 32 x 132 f32
constexpr int CS_STRIDE = 132;
constexpr int PS_SMEM = PS_CS + 32 * CS_STRIDE * 4;   // 201216 B

__global__ void __launch_bounds__(128) lstm_persistent() {
    extern __shared__ __align__(128) char smem[];
    const uint32_t sb = smem_u32(smem);
    float* Cs = (float*)(smem + PS_CS);
    const int tid = threadIdx.x, lane = tid & 31, wn = tid >> 5;  // 4 warps along n
    const int n0 = blockIdx.x * 128;
    const int b0 = blockIdx.y * 32;
    unsigned* const ctr = &g_ctrs[blockIdx.y];        // per-b-group barrier, fan-in 16

    const uint32_t aoff = a_lane_off(lane);
    const uint32_t boff = b_lane_off(lane);

    // Resident B: W_h tile 128(n) x 512(k), 8 chunks, loaded once.
#pragma unroll
    for (int c = 0; c < 8; c++) {
#pragma unroll
        for (int q = 0; q < 8; q++) {
            int i = tid + q * 128, r = i >> 3, g = i & 7;
            cp16(sb + PS_B + c * B_CHUNK + r * RSTRIDE + g * 16,
                 g_Whh + (size_t)(n0 + r) * Hh + c * 64 + g * 8);
        }
    }
    CP_COMMIT();

    // Epilogue mapping: thread -> (batch row, 8-j segment); c in regs.
    const int erow = tid >> 2, ejq = tid & 3;         // 32 rows x 4 segs
    const int eb = b0 + erow;
    const int j0 = n0 >> 2;
    float cv[8];
#pragma unroll
    for (int j = 0; j < 8; j++) cv[j] = 0.0f;

    CP_WAIT(0);
    __syncthreads();

    auto compute_chunk = [&](int kc, float (&acc)[2][4][4]) {
        const uint32_t Ab = sb + PS_A + kc * A_CHUNK;
        const uint32_t Bx = sb + PS_B + kc * B_CHUNK + (wn * 32) * RSTRIDE;
#pragma unroll
        for (int kb = 0; kb < 64; kb += 16) {
            uint32_t a[2][4], b[2][4];
#pragma unroll
            for (int mi = 0; mi < 2; mi++)
                ldm_x4(a[mi], Ab + mi * 16 * RSTRIDE + kb * 2 + aoff);
#pragma unroll
            for (int bi = 0; bi < 2; bi++)
                ldm_x4(b[bi], Bx + bi * 16 * RSTRIDE + kb * 2 + boff);
#pragma unroll
            for (int mi = 0; mi < 2; mi++)
#pragma unroll
                for (int ni = 0; ni < 4; ni++)
                    mma16816(acc[mi][ni], a[mi], &b[ni >> 1][(ni & 1) * 2]);
        }
    };
    auto load_hchunk = [&](const __half* hin, int c) {
#pragma unroll
        for (int q = 0; q < 2; q++) {
            int i = tid + q * 128, r = i >> 3, g = i & 7;
            cp16(sb + PS_A + c * A_CHUNK + r * RSTRIDE + g * 16,
                 hin + (size_t)(b0 + r) * Hh + c * 64 + g * 8);
        }
    };

    for (int t = 0; t < Tt; t++) {
        const __half* __restrict__ hin  = g_hh[t & 1];
        __half* __restrict__ hout       = g_hh[(t + 1) & 1];

        // gx(t) prefetch into registers (no barrier dependency; ~2us to use)
        uint4 gxp[4];
        {
            const uint4* gsrc = (const uint4*)(g_gx + ((size_t)t * Bb + eb) * G4 + n0 + ejq * 32);
#pragma unroll
            for (int i = 0; i < 4; i++) gxp[i] = gsrc[i];
        }

        // h loads: 2 commit groups of 4 chunks
        load_hchunk(hin, 0); load_hchunk(hin, 1);
        load_hchunk(hin, 2); load_hchunk(hin, 3); CP_COMMIT();
        load_hchunk(hin, 4); load_hchunk(hin, 5);
        load_hchunk(hin, 6); load_hchunk(hin, 7); CP_COMMIT();

        float acc[2][4][4] = {};
        CP_WAIT(1);
        __syncthreads();
        compute_chunk(0, acc); compute_chunk(1, acc);
        compute_chunk(2, acc); compute_chunk(3, acc);
        CP_WAIT(0);
        __syncthreads();
        compute_chunk(4, acc); compute_chunk(5, acc);
        compute_chunk(6, acc); compute_chunk(7, acc);

        // Exchange accumulators through smem (Cs[32][132])
        const int r0 = lane >> 2;
        const int c0 = wn * 32 + 2 * (lane & 3);
#pragma unroll
        for (int mi = 0; mi < 2; mi++) {
#pragma unroll
            for (int ni = 0; ni < 4; ni++) {
                const int rr = r0 + mi * 16, cc = c0 + ni * 8;
                Cs[rr * CS_STRIDE + cc]           = acc[mi][ni][0];
                Cs[rr * CS_STRIDE + cc + 1]       = acc[mi][ni][1];
                Cs[(rr + 8) * CS_STRIDE + cc]     = acc[mi][ni][2];
                Cs[(rr + 8) * CS_STRIDE + cc + 1] = acc[mi][ni][3];
            }
        }
        __syncthreads();

        // Pointwise LSTM update: 8 j's per thread; gx from registers
        {
            const float* cs = Cs + erow * CS_STRIDE + ejq * 32;
            const uint32_t* gxh2 = (const uint32_t*)gxp;   // 8 x (2 halves) pairs
            __half hb[8];
#pragma unroll
            for (int j = 0; j < 8; j++) {
                float4 pre = *(const float4*)(cs + j * 4);           // W_h·h (f,i,c,o)
                float2 g01 = __half22float2(*(const __half2*)&gxh2[j * 2]);
                float2 g23 = __half22float2(*(const __half2*)&gxh2[j * 2 + 1]);
                float fg = sigf(pre.x + g01.x);
                float ig = sigf(pre.y + g01.y);
                float gg = tanhf_(pre.z + g23.x);
                float og = sigf(pre.w + g23.y);
                float cn = fg * cv[j] + ig * gg;
                cv[j] = cn;
                hb[j] = __float2half_rn(og * tanhf_(cn));
            }
            *(uint4*)(hout + (size_t)eb * Hh + j0 + ejq * 8) = *(uint4*)hb;
        }

        // Per-b-group barrier: release h(t+1), tight acquire spin
        __threadfence();
        __syncthreads();
        if (tid == 0) {
            asm volatile("red.release.gpu.global.add.u32 [%0], %1;"
                         :: "l"(ctr), "r"(1u) : "memory");
            const unsigned target = (unsigned)(t + 1) * 16u;
            unsigned v;
            do {
                asm volatile("ld.acquire.gpu.global.u32 %0, [%1];"
                             : "=r"(v) : "l"(ctr) : "memory");
            } while (v < target);
        }
        __syncthreads();
    }
}

// ---------------------------------------------------------------------------
// Output head: logits = h_last @ Wout + bout; log_softmax per row.
// ---------------------------------------------------------------------------
__global__ __launch_bounds__(256) void final_head(
    const float* __restrict__ Wout, const float* __restrict__ bout,
    float* __restrict__ out)
{
    __shared__ float hs[Hh];
    __shared__ float red[256];

    const int b = blockIdx.x;
    const int o = threadIdx.x;
    const __half* hrow = g_hh[0] + (size_t)b * Hh;   // t=511 wrote buffer 0

    for (int k = o; k < Hh; k += 256) hs[k] = __half2float(hrow[k]);
    __syncthreads();

    float acc = bout[o];
#pragma unroll 4
    for (int k = 0; k < Hh; k++)
        acc += hs[k] * Wout[(size_t)k * Oo + o];

    red[o] = acc;
    __syncthreads();
    for (int s = 128; s > 0; s >>= 1) {
        if (o < s) red[o] = fmaxf(red[o], red[o + s]);
        __syncthreads();
    }
    const float mx = red[0];
    __syncthreads();

    red[o] = expf(acc - mx);
    __syncthreads();
    for (int s = 128; s > 0; s >>= 1) {
        if (o < s) red[o] += red[o + s];
        __syncthreads();
    }
    const float lse = logf(red[0]) + mx;
    out[(size_t)b * Oo + o] = acc - lse;
}

// ---------------------------------------------------------------------------
// kernel_launch
// ---------------------------------------------------------------------------
extern "C" void kernel_launch(void* const* d_in, const int* in_sizes, int n_in,
                              void* d_out, int out_size)
{
    const float* inputs = (const float*)d_in[0];
    const float* Wf = (const float*)d_in[1];
    const float* bf = (const float*)d_in[2];
    const float* Wi = (const float*)d_in[3];
    const float* bi = (const float*)d_in[4];
    const float* Wc = (const float*)d_in[5];
    const float* bc = (const float*)d_in[6];
    const float* Wo = (const float*)d_in[7];
    const float* bo = (const float*)d_in[8];
    const float* Wout = (const float*)d_in[9];
    const float* bout = (const float*)d_in[10];
    float* out = (float*)d_out;

    static bool attr_done = false;
    if (!attr_done) {
        cudaFuncSetAttribute(phase1_mma, cudaFuncAttributeMaxDynamicSharedMemorySize, P1_SMEM);
        cudaFuncSetAttribute(lstm_persistent, cudaFuncAttributeMaxDynamicSharedMemorySize, PS_SMEM);
        attr_done = true;
    }

    pack_x<<<(unsigned)((size_t)Tt * Bb * Ii / 4 / 256), 256>>>(inputs);
    pack_w<<<dim3(G4 / 64, (Ii + Hh) / 64), 256>>>(Wf, bf, Wi, bi, Wc, bc, Wo, bo);
    zero_state<<<(Bb * Hh + 255) / 256, 256>>>();

    // Phase 1 (B-resident streaming): 16 n-tiles x 16 m-groups = 256 CTAs
    phase1_mma<<<dim3(G4 / 128, 16), 256, P1_SMEM>>>();

    // Persistent recurrence: 16 n-tiles x 8 b-groups = 128 CTAs, single wave
    lstm_persistent<<<dim3(G4 / 128, Bb / 32), 128, PS_SMEM>>>();

    final_head<<<Bb, 256>>>(Wout, bout, out);
}

// round 15
// speedup vs baseline: 1.0450x; 1.0450x over previous
#include <cuda_runtime.h>
#include <cuda_fp16.h>
#include <math.h>
#include <stdint.h>

// Problem constants
constexpr int Bb = 256;    // batch
constexpr int Tt = 512;    // seq len
constexpr int Ii = 256;    // input size
constexpr int Hh = 512;    // hidden size
constexpr int Oo = 256;    // output size
constexpr int G4 = 4 * Hh; // 2048 packed gate width, n = j*4 + g (0=f,1=i,2=c,3=o)

// ---------------------------------------------------------------------------
// Device scratch
// ---------------------------------------------------------------------------
__device__ __half g_gx[(size_t)Tt * Bb * G4];   // 512 MB: input projections fp16, m = t*B+b
__device__ __half g_xh[(size_t)Tt * Bb * Ii];   // 64 MB: x fp16, [m][k]
__device__ __half g_Wxh[(size_t)G4 * Ii];       // W_x packed [n][k] fp16
__device__ __half g_Whh[(size_t)G4 * Hh];       // W_h packed [n][k] fp16
__device__ float  g_biasp[G4];                  // bias packed [n]
__device__ __half g_hh[2][Bb * Hh];             // double-buffered hidden (fp16)
__device__ unsigned g_ctrs[8];                  // per-b-group barrier counters

// ---------------------------------------------------------------------------
// PTX helpers (base PTX only: valid at compute_103 virtual arch)
// ---------------------------------------------------------------------------
__device__ __forceinline__ uint32_t smem_u32(const void* p) {
    uint32_t a;
    asm("{ .reg .u64 t; cvta.to.shared.u64 t, %1; cvt.u32.u64 %0, t; }" : "=r"(a) : "l"(p));
    return a;
}
__device__ __forceinline__ void cp16(uint32_t dst, const void* src) {
    asm volatile("cp.async.cg.shared.global [%0], [%1], 16;" :: "r"(dst), "l"(src));
}
#define CP_COMMIT() asm volatile("cp.async.commit_group;" ::: "memory")
#define CP_WAIT(n)  asm volatile("cp.async.wait_group %0;" :: "n"(n) : "memory")

__device__ __forceinline__ void ldm_x4(uint32_t (&r)[4], uint32_t addr) {
    asm volatile("ldmatrix.sync.aligned.m8n8.x4.shared.b16 {%0,%1,%2,%3}, [%4];"
        : "=r"(r[0]), "=r"(r[1]), "=r"(r[2]), "=r"(r[3]) : "r"(addr));
}
__device__ __forceinline__ void mma16816(float (&c)[4], const uint32_t (&a)[4], const uint32_t* b) {
    asm volatile("mma.sync.aligned.m16n8k16.row.col.f32.f16.f16.f32 "
        "{%0,%1,%2,%3}, {%4,%5,%6,%7}, {%8,%9}, {%0,%1,%2,%3};"
        : "+f"(c[0]), "+f"(c[1]), "+f"(c[2]), "+f"(c[3])
        : "r"(a[0]), "r"(a[1]), "r"(a[2]), "r"(a[3]), "r"(b[0]), "r"(b[1]));
}

// Fast activations (err ~1e-7, below fp16 noise)
__device__ __forceinline__ float ex2f(float x) { float y; asm("ex2.approx.f32 %0, %1;" : "=f"(y) : "f"(x)); return y; }
__device__ __forceinline__ float rcpf(float x) { float y; asm("rcp.approx.f32 %0, %1;" : "=f"(y) : "f"(x)); return y; }
__device__ __forceinline__ float sigf(float x)   { return rcpf(1.0f + ex2f(-1.4426950408889634f * x)); }
__device__ __forceinline__ float tanhf_(float x) { return __fmaf_rn(2.0f, sigf(2.0f * x), -1.0f); }

// SMEM tile geometry: 64 data halves + 8 pad per row -> conflict-free ldmatrix
constexpr int RSTRIDE = 144;   // bytes per smem row

__device__ __forceinline__ uint32_t a_lane_off(int lane) {
    return (uint32_t)(((lane & 7) + ((lane >> 3) & 1) * 8) * RSTRIDE + (lane >> 4) * 16);
}
__device__ __forceinline__ uint32_t b_lane_off(int lane) {
    return (uint32_t)(((lane & 7) + ((lane >> 4) & 1) * 8) * RSTRIDE + ((lane >> 3) & 1) * 16);
}

// ---------------------------------------------------------------------------
// Packing
// ---------------------------------------------------------------------------
__global__ void pack_x(const float* __restrict__ x) {
    size_t e = ((size_t)blockIdx.x * blockDim.x + threadIdx.x) * 4;
    if (e >= (size_t)Tt * Bb * Ii) return;
    int    k  = (int)(e & 255);
    size_t md = e >> 8;
    int    b  = (int)(md & 255);
    int    t  = (int)(md >> 8);
    float4 v = *(const float4*)(x + ((size_t)b * Tt + t) * Ii + k);
    *(__half2*)(g_xh + e)     = __floats2half2_rn(v.x, v.y);
    *(__half2*)(g_xh + e + 2) = __floats2half2_rn(v.z, v.w);
}

// Tiled transpose pack for weights: 64n x 64k tiles through smem,
// fully coalesced 16B writes (validated in R13/R14).
__global__ void pack_w(const float* __restrict__ Wf, const float* __restrict__ bf,
                       const float* __restrict__ Wi, const float* __restrict__ bi,
                       const float* __restrict__ Wc, const float* __restrict__ bc,
                       const float* __restrict__ Wo, const float* __restrict__ bo) {
    __shared__ __half ws[64][72];   // [kk][nn]
    const int n0 = blockIdx.x * 64;
    const int k0 = blockIdx.y * 64;
    const float* Ws[4] = {Wf, Wi, Wc, Wo};

#pragma unroll
    for (int p = 0; p < 16; p++) {
        int idx = threadIdx.x + p * 256;
        int kk = idx >> 6, nn = idx & 63;
        int n = n0 + nn, g = n & 3, j = n >> 2;
        ws[kk][nn] = __float2half_rn(Ws[g][(size_t)(k0 + kk) * Hh + j]);
    }
    __syncthreads();

    const int nn = threadIdx.x >> 2, kq = threadIdx.x & 3;
    const int n = n0 + nn;
    __align__(16) __half tmp[16];
#pragma unroll
    for (int i = 0; i < 16; i++) tmp[i] = ws[kq * 16 + i][nn];
    if (k0 < Ii) {
        __half* dst = g_Wxh + (size_t)n * Ii + k0 + kq * 16;
        *(uint4*)dst       = *(uint4*)tmp;
        *(uint4*)(dst + 8) = *(uint4*)(tmp + 8);
    } else {
        __half* dst = g_Whh + (size_t)n * Hh + (k0 - Ii) + kq * 16;
        *(uint4*)dst       = *(uint4*)tmp;
        *(uint4*)(dst + 8) = *(uint4*)(tmp + 8);
    }

    if (blockIdx.y == 0 && threadIdx.x < 64) {
        int nb = n0 + threadIdx.x, g = nb & 3, j = nb >> 2;
        const float* bs[4] = {bf, bi, bc, bo};
        g_biasp[nb] = bs[g][j];
    }
}

__global__ void zero_state() {
    int i = blockIdx.x * blockDim.x + threadIdx.x;
    if (i < 8) g_ctrs[i] = 0;
    if (i < Bb * Hh) g_hh[0][i] = __float2half_rn(0.0f);
}

// ---------------------------------------------------------------------------
// Phase 1: gx[m][n] = fp16( sum_k xh[m][k] * Wxh[n][k] + bias[n] )
//   CTA 128(M) x 128(N), 256 thr (8 warps = 2m x 4n, 64x32 warp tiles),
//   K=256 in 4 stages, cp.async pipeline DEPTH 3 (two compute-stages of
//   load slack per stage boundary). smem 110.6KB -> 2 CTAs/SM.
// ---------------------------------------------------------------------------
constexpr int P1_ST = 18432;                        // one 128x64h tile
constexpr uint32_t P1_A0 = 0,           P1_B0 = P1_ST;
constexpr uint32_t P1_A1 = 2 * P1_ST,   P1_B1 = 3 * P1_ST;
constexpr uint32_t P1_A2 = 4 * P1_ST,   P1_B2 = 5 * P1_ST;
constexpr int P1_SMEM = 6 * P1_ST;                  // 110592 B

__global__ void __launch_bounds__(256) phase1_mma() {
    extern __shared__ __align__(128) char smem[];
    const uint32_t sb = smem_u32(smem);
    const int tid = threadIdx.x, lane = tid & 31, wid = tid >> 5;
    const int wm = wid >> 2, wn = wid & 3;
    const int n0 = blockIdx.x * 128;
    const int m0 = blockIdx.y * 128;

    const uint32_t aoff = a_lane_off(lane);
    const uint32_t boff = b_lane_off(lane);

    const uint32_t Abuf[3] = {sb + P1_A0, sb + P1_A1, sb + P1_A2};
    const uint32_t Bbuf[3] = {sb + P1_B0, sb + P1_B1, sb + P1_B2};

    float acc[4][4][4] = {};

    auto load_stage = [&](int s) {
        const int kb0 = s * 64;
        const uint32_t Ab = Abuf[s % 3], Bx = Bbuf[s % 3];
#pragma unroll
        for (int q = 0; q < 4; q++) {                       // A: 128 x 64h
            int i = tid + q * 256, r = i >> 3, g = i & 7;
            cp16(Ab + r * RSTRIDE + g * 16, g_xh + (size_t)(m0 + r) * Ii + kb0 + g * 8);
        }
#pragma unroll
        for (int q = 0; q < 4; q++) {                       // B: 128 x 64h
            int i = tid + q * 256, r = i >> 3, g = i & 7;
            cp16(Bx + r * RSTRIDE + g * 16, g_Wxh + (size_t)(n0 + r) * Ii + kb0 + g * 8);
        }
        CP_COMMIT();
    };
    auto compute = [&](int s) {
        const uint32_t Ab = Abuf[s % 3], Bx = Bbuf[s % 3];
#pragma unroll
        for (int kb = 0; kb < 64; kb += 16) {
            uint32_t a[4][4], b[2][4];
#pragma unroll
            for (int mi = 0; mi < 4; mi++)
                ldm_x4(a[mi], Ab + (wm * 64 + mi * 16) * RSTRIDE + kb * 2 + aoff);
#pragma unroll
            for (int bi = 0; bi < 2; bi++)
                ldm_x4(b[bi], Bx + (wn * 32 + bi * 16) * RSTRIDE + kb * 2 + boff);
#pragma unroll
            for (int mi = 0; mi < 4; mi++)
#pragma unroll
                for (int ni = 0; ni < 4; ni++)
                    mma16816(acc[mi][ni], a[mi], &b[ni >> 1][(ni & 1) * 2]);
        }
    };

    load_stage(0); load_stage(1); load_stage(2);
#pragma unroll
    for (int s = 0; s < 4; s++) {
        if (s == 0)      { CP_WAIT(2); }
        else if (s == 1) { CP_WAIT(2); }   // stage 3 committed during s=0
        else if (s == 2) { CP_WAIT(1); }
        else             { CP_WAIT(0); }
        __syncthreads();
        compute(s);
        __syncthreads();
        if (s == 0) load_stage(3);
    }

    // Epilogue: fp16 store with bias
    const int r0 = wm * 64 + (lane >> 2);
    const int c0 = wn * 32 + 2 * (lane & 3);
#pragma unroll
    for (int mi = 0; mi < 4; mi++) {
#pragma unroll
        for (int ni = 0; ni < 4; ni++) {
            const int n = n0 + c0 + ni * 8;
            const float2 bv = *(const float2*)&g_biasp[n];
            const int m = m0 + r0 + mi * 16;
            *(__half2*)(g_gx + (size_t)m * G4 + n) =
                __floats2half2_rn(acc[mi][ni][0] + bv.x, acc[mi][ni][1] + bv.y);
            *(__half2*)(g_gx + (size_t)(m + 8) * G4 + n) =
                __floats2half2_rn(acc[mi][ni][2] + bv.x, acc[mi][ni][3] + bv.y);
        }
    }
}

// ---------------------------------------------------------------------------
// Persistent recurrence (R7, verbatim): 128 CTAs = 16 n-tiles(128) x 8
// b-groups(32), all 512 steps. 128 threads (4 warps along n, 32x32 warp
// tiles). W_h tile (144KB) resident in smem; c in registers; gx prefetched
// into registers from global; per-b-group spin barrier (fan-in 16).
// ---------------------------------------------------------------------------
constexpr int A_CHUNK = 32 * RSTRIDE;                 // 4608 B  (32 rows x 64 halves)
constexpr int B_CHUNK = 128 * RSTRIDE;                // 18432 B (128 rows x 64 halves)
constexpr uint32_t PS_A  = 0;                         // A (h) chunks: 8 x 4608 = 36864
constexpr uint32_t PS_B  = 8 * A_CHUNK;               // B (Wh) resident: 8 x 18432 = 147456
constexpr uint32_t PS_CS = PS_B + 8 * B_CHUNK;        // Cs exchange: 32 x 132 f32
constexpr int CS_STRIDE = 132;
constexpr int PS_SMEM = PS_CS + 32 * CS_STRIDE * 4;   // 201216 B

__global__ void __launch_bounds__(128) lstm_persistent() {
    extern __shared__ __align__(128) char smem[];
    const uint32_t sb = smem_u32(smem);
    float* Cs = (float*)(smem + PS_CS);
    const int tid = threadIdx.x, lane = tid & 31, wn = tid >> 5;  // 4 warps along n
    const int n0 = blockIdx.x * 128;
    const int b0 = blockIdx.y * 32;
    unsigned* const ctr = &g_ctrs[blockIdx.y];        // per-b-group barrier, fan-in 16

    const uint32_t aoff = a_lane_off(lane);
    const uint32_t boff = b_lane_off(lane);

    // Resident B: W_h tile 128(n) x 512(k), 8 chunks, loaded once.
#pragma unroll
    for (int c = 0; c < 8; c++) {
#pragma unroll
        for (int q = 0; q < 8; q++) {
            int i = tid + q * 128, r = i >> 3, g = i & 7;
            cp16(sb + PS_B + c * B_CHUNK + r * RSTRIDE + g * 16,
                 g_Whh + (size_t)(n0 + r) * Hh + c * 64 + g * 8);
        }
    }
    CP_COMMIT();

    // Epilogue mapping: thread -> (batch row, 8-j segment); c in regs.
    const int erow = tid >> 2, ejq = tid & 3;         // 32 rows x 4 segs
    const int eb = b0 + erow;
    const int j0 = n0 >> 2;
    float cv[8];
#pragma unroll
    for (int j = 0; j < 8; j++) cv[j] = 0.0f;

    CP_WAIT(0);
    __syncthreads();

    auto compute_chunk = [&](int kc, float (&acc)[2][4][4]) {
        const uint32_t Ab = sb + PS_A + kc * A_CHUNK;
        const uint32_t Bx = sb + PS_B + kc * B_CHUNK + (wn * 32) * RSTRIDE;
#pragma unroll
        for (int kb = 0; kb < 64; kb += 16) {
            uint32_t a[2][4], b[2][4];
#pragma unroll
            for (int mi = 0; mi < 2; mi++)
                ldm_x4(a[mi], Ab + mi * 16 * RSTRIDE + kb * 2 + aoff);
#pragma unroll
            for (int bi = 0; bi < 2; bi++)
                ldm_x4(b[bi], Bx + bi * 16 * RSTRIDE + kb * 2 + boff);
#pragma unroll
            for (int mi = 0; mi < 2; mi++)
#pragma unroll
                for (int ni = 0; ni < 4; ni++)
                    mma16816(acc[mi][ni], a[mi], &b[ni >> 1][(ni & 1) * 2]);
        }
    };
    auto load_hchunk = [&](const __half* hin, int c) {
#pragma unroll
        for (int q = 0; q < 2; q++) {
            int i = tid + q * 128, r = i >> 3, g = i & 7;
            cp16(sb + PS_A + c * A_CHUNK + r * RSTRIDE + g * 16,
                 hin + (size_t)(b0 + r) * Hh + c * 64 + g * 8);
        }
    };

    for (int t = 0; t < Tt; t++) {
        const __half* __restrict__ hin  = g_hh[t & 1];
        __half* __restrict__ hout       = g_hh[(t + 1) & 1];

        // gx(t) prefetch into registers (no barrier dependency; ~2us to use)
        uint4 gxp[4];
        {
            const uint4* gsrc = (const uint4*)(g_gx + ((size_t)t * Bb + eb) * G4 + n0 + ejq * 32);
#pragma unroll
            for (int i = 0; i < 4; i++) gxp[i] = gsrc[i];
        }

        // h loads: 2 commit groups of 4 chunks
        load_hchunk(hin, 0); load_hchunk(hin, 1);
        load_hchunk(hin, 2); load_hchunk(hin, 3); CP_COMMIT();
        load_hchunk(hin, 4); load_hchunk(hin, 5);
        load_hchunk(hin, 6); load_hchunk(hin, 7); CP_COMMIT();

        float acc[2][4][4] = {};
        CP_WAIT(1);
        __syncthreads();
        compute_chunk(0, acc); compute_chunk(1, acc);
        compute_chunk(2, acc); compute_chunk(3, acc);
        CP_WAIT(0);
        __syncthreads();
        compute_chunk(4, acc); compute_chunk(5, acc);
        compute_chunk(6, acc); compute_chunk(7, acc);

        // Exchange accumulators through smem (Cs[32][132])
        const int r0 = lane >> 2;
        const int c0 = wn * 32 + 2 * (lane & 3);
#pragma unroll
        for (int mi = 0; mi < 2; mi++) {
#pragma unroll
            for (int ni = 0; ni < 4; ni++) {
                const int rr = r0 + mi * 16, cc = c0 + ni * 8;
                Cs[rr * CS_STRIDE + cc]           = acc[mi][ni][0];
                Cs[rr * CS_STRIDE + cc + 1]       = acc[mi][ni][1];
                Cs[(rr + 8) * CS_STRIDE + cc]     = acc[mi][ni][2];
                Cs[(rr + 8) * CS_STRIDE + cc + 1] = acc[mi][ni][3];
            }
        }
        __syncthreads();

        // Pointwise LSTM update: 8 j's per thread; gx from registers
        {
            const float* cs = Cs + erow * CS_STRIDE + ejq * 32;
            const uint32_t* gxh2 = (const uint32_t*)gxp;   // 8 x (2 halves) pairs
            __half hb[8];
#pragma unroll
            for (int j = 0; j < 8; j++) {
                float4 pre = *(const float4*)(cs + j * 4);           // W_h·h (f,i,c,o)
                float2 g01 = __half22float2(*(const __half2*)&gxh2[j * 2]);
                float2 g23 = __half22float2(*(const __half2*)&gxh2[j * 2 + 1]);
                float fg = sigf(pre.x + g01.x);
                float ig = sigf(pre.y + g01.y);
                float gg = tanhf_(pre.z + g23.x);
                float og = sigf(pre.w + g23.y);
                float cn = fg * cv[j] + ig * gg;
                cv[j] = cn;
                hb[j] = __float2half_rn(og * tanhf_(cn));
            }
            *(uint4*)(hout + (size_t)eb * Hh + j0 + ejq * 8) = *(uint4*)hb;
        }

        // Per-b-group barrier: release h(t+1), tight acquire spin
        __threadfence();
        __syncthreads();
        if (tid == 0) {
            asm volatile("red.release.gpu.global.add.u32 [%0], %1;"
                         :: "l"(ctr), "r"(1u) : "memory");
            const unsigned target = (unsigned)(t + 1) * 16u;
            unsigned v;
            do {
                asm volatile("ld.acquire.gpu.global.u32 %0, [%1];"
                             : "=r"(v) : "l"(ctr) : "memory");
            } while (v < target);
        }
        __syncthreads();
    }
}

// ---------------------------------------------------------------------------
// Output head: logits = h_last @ Wout + bout; log_softmax per row.
// ---------------------------------------------------------------------------
__global__ __launch_bounds__(256) void final_head(
    const float* __restrict__ Wout, const float* __restrict__ bout,
    float* __restrict__ out)
{
    __shared__ float hs[Hh];
    __shared__ float red[256];

    const int b = blockIdx.x;
    const int o = threadIdx.x;
    const __half* hrow = g_hh[0] + (size_t)b * Hh;   // t=511 wrote buffer 0

    for (int k = o; k < Hh; k += 256) hs[k] = __half2float(hrow[k]);
    __syncthreads();

    float acc = bout[o];
#pragma unroll 4
    for (int k = 0; k < Hh; k++)
        acc += hs[k] * Wout[(size_t)k * Oo + o];

    red[o] = acc;
    __syncthreads();
    for (int s = 128; s > 0; s >>= 1) {
        if (o < s) red[o] = fmaxf(red[o], red[o + s]);
        __syncthreads();
    }
    const float mx = red[0];
    __syncthreads();

    red[o] = expf(acc - mx);
    __syncthreads();
    for (int s = 128; s > 0; s >>= 1) {
        if (o < s) red[o] += red[o + s];
        __syncthreads();
    }
    const float lse = logf(red[0]) + mx;
    out[(size_t)b * Oo + o] = acc - lse;
}

// ---------------------------------------------------------------------------
// kernel_launch
// ---------------------------------------------------------------------------
extern "C" void kernel_launch(void* const* d_in, const int* in_sizes, int n_in,
                              void* d_out, int out_size)
{
    const float* inputs = (const float*)d_in[0];
    const float* Wf = (const float*)d_in[1];
    const float* bf = (const float*)d_in[2];
    const float* Wi = (const float*)d_in[3];
    const float* bi = (const float*)d_in[4];
    const float* Wc = (const float*)d_in[5];
    const float* bc = (const float*)d_in[6];
    const float* Wo = (const float*)d_in[7];
    const float* bo = (const float*)d_in[8];
    const float* Wout = (const float*)d_in[9];
    const float* bout = (const float*)d_in[10];
    float* out = (float*)d_out;

    static bool attr_done = false;
    if (!attr_done) {
        cudaFuncSetAttribute(phase1_mma, cudaFuncAttributeMaxDynamicSharedMemorySize, P1_SMEM);
        cudaFuncSetAttribute(lstm_persistent, cudaFuncAttributeMaxDynamicSharedMemorySize, PS_SMEM);
        attr_done = true;
    }

    pack_x<<<(unsigned)((size_t)Tt * Bb * Ii / 4 / 256), 256>>>(inputs);
    pack_w<<<dim3(G4 / 64, (Ii + Hh) / 64), 256>>>(Wf, bf, Wi, bi, Wc, bc, Wo, bo);
    zero_state<<<(Bb * Hh + 255) / 256, 256>>>();

    // Phase 1: M = 131072, N = 2048, K = 256, 128x128 tiles, depth-3 pipeline
    phase1_mma<<<dim3(G4 / 128, (Tt * Bb) / 128), 256, P1_SMEM>>>();

    // Persistent recurrence: 16 n-tiles x 8 b-groups = 128 CTAs, single wave
    lstm_persistent<<<dim3(G4 / 128, Bb / 32), 128, PS_SMEM>>>();

    final_head<<<Bb, 256>>>(Wout, bout, out);
}